// round 1
// baseline (speedup 1.0000x reference)
#include <cuda_runtime.h>
#include <math.h>

// Problem constants
#define MDIM 4096          // B*T rows
#define CDIM 1024          // embedding
#define T_SEQ 2048
#define N_H 16
#define D_HEAD 64

// Scratch (device globals; allocation-free per harness rules)
__device__ float g_q[MDIM * CDIM];
__device__ float g_k[MDIM * CDIM];
__device__ float g_v[MDIM * CDIM];
__device__ float g_y[MDIM * CDIM];

// ---------------------------------------------------------------------------
// SGEMM body: C[M=4096, N=1024] = A[4096,1024] @ W[1024,1024] (+bias)
// 128x128 block tile, 8x8 per thread, 256 threads, K-tile 8.
// ---------------------------------------------------------------------------
__device__ __forceinline__ void gemm_body(const float* __restrict__ A,
                                          const float* __restrict__ W,
                                          const float* __restrict__ bias,
                                          float* __restrict__ C)
{
    const int N = CDIM, K = CDIM;
    __shared__ float As[8][128];
    __shared__ float Bs[8][128];

    const int tid = threadIdx.x;
    const int tx = tid & 15;
    const int ty = tid >> 4;
    const int row0 = blockIdx.y * 128;
    const int col0 = blockIdx.x * 128;

    float acc[8][8];
#pragma unroll
    for (int i = 0; i < 8; i++)
#pragma unroll
        for (int j = 0; j < 8; j++) acc[i][j] = 0.f;

    const int arow  = tid >> 1;          // 0..127
    const int ak4   = (tid & 1) * 4;     // 0 or 4
    const int brow  = tid >> 5;          // 0..7
    const int bcol4 = (tid & 31) * 4;    // 0..124

    const float* Aptr = A + (size_t)(row0 + arow) * K + ak4;
    const float* Bptr = W + (size_t)brow * N + col0 + bcol4;

    for (int k0 = 0; k0 < K; k0 += 8) {
        float4 av = *(const float4*)(Aptr + k0);
        float4 bv = *(const float4*)(Bptr + (size_t)k0 * N);
        As[ak4 + 0][arow] = av.x;
        As[ak4 + 1][arow] = av.y;
        As[ak4 + 2][arow] = av.z;
        As[ak4 + 3][arow] = av.w;
        *(float4*)&Bs[brow][bcol4] = bv;
        __syncthreads();
#pragma unroll
        for (int kk = 0; kk < 8; kk++) {
            float4 a0 = *(const float4*)&As[kk][ty * 8];
            float4 a1 = *(const float4*)&As[kk][ty * 8 + 4];
            float4 b0 = *(const float4*)&Bs[kk][tx * 8];
            float4 b1 = *(const float4*)&Bs[kk][tx * 8 + 4];
            float a[8] = {a0.x, a0.y, a0.z, a0.w, a1.x, a1.y, a1.z, a1.w};
            float b[8] = {b0.x, b0.y, b0.z, b0.w, b1.x, b1.y, b1.z, b1.w};
#pragma unroll
            for (int i = 0; i < 8; i++)
#pragma unroll
                for (int j = 0; j < 8; j++)
                    acc[i][j] = fmaf(a[i], b[j], acc[i][j]);
        }
        __syncthreads();
    }

#pragma unroll
    for (int i = 0; i < 8; i++) {
        int r = row0 + ty * 8 + i;
        float* crow = C + (size_t)r * N + col0 + tx * 8;
#pragma unroll
        for (int j = 0; j < 8; j += 4) {
            float4 v = make_float4(acc[i][j], acc[i][j + 1], acc[i][j + 2], acc[i][j + 3]);
            if (bias) {
                int c = col0 + tx * 8 + j;
                v.x += bias[c + 0];
                v.y += bias[c + 1];
                v.z += bias[c + 2];
                v.w += bias[c + 3];
            }
            *(float4*)(crow + j) = v;
        }
    }
}

// Fused QKV projections: blockIdx.z picks which weight/output.
__global__ __launch_bounds__(256) void qkv_gemm_kernel(const float* __restrict__ x,
                                                       const float* __restrict__ Wq,
                                                       const float* __restrict__ Wk,
                                                       const float* __restrict__ Wv)
{
    const float* W = (blockIdx.z == 0) ? Wq : (blockIdx.z == 1) ? Wk : Wv;
    float* C = (blockIdx.z == 0) ? g_q : (blockIdx.z == 1) ? g_k : g_v;
    gemm_body(x, W, nullptr, C);
}

__global__ __launch_bounds__(256) void out_gemm_kernel(const float* __restrict__ Wo,
                                                       const float* __restrict__ bo,
                                                       float* __restrict__ out)
{
    gemm_body(g_y, Wo, bo, out);
}

// ---------------------------------------------------------------------------
// Flash attention (fp32, causal). One thread = one query row.
// Block: 128 threads = 128 query rows. KV tiles of 32 staged in SMEM.
// grid: (T/128, H, B)
// ---------------------------------------------------------------------------
#define KV_TILE 32

__global__ __launch_bounds__(128) void flash_kernel()
{
    __shared__ float Ks[KV_TILE][D_HEAD];
    __shared__ float Vs[KV_TILE][D_HEAD];

    const int tid = threadIdx.x;
    const int b = blockIdx.z;
    const int h = blockIdx.y;
    const int t = blockIdx.x * 128 + tid;
    const float scale = 0.125f;  // 1/sqrt(64)

    // Load & pre-scale this thread's q row.
    const float* qrow = g_q + ((size_t)(b * T_SEQ + t)) * CDIM + h * D_HEAD;
    float q[D_HEAD];
#pragma unroll
    for (int d = 0; d < D_HEAD; d += 4) {
        float4 v = *(const float4*)(qrow + d);
        q[d + 0] = v.x * scale;
        q[d + 1] = v.y * scale;
        q[d + 2] = v.z * scale;
        q[d + 3] = v.w * scale;
    }

    float o[D_HEAD];
#pragma unroll
    for (int d = 0; d < D_HEAD; d++) o[d] = 0.f;
    float m = -INFINITY, l = 0.f;

    const int kv_end = blockIdx.x * 128 + 128;  // max keys needed by this block

#pragma unroll 1
    for (int j0 = 0; j0 < kv_end; j0 += KV_TILE) {
        // Cooperative tile load: 32x64 floats each, 4 float4 per thread.
        {
            const size_t gbase = ((size_t)(b * T_SEQ + j0)) * CDIM + h * D_HEAD;
#pragma unroll
            for (int i = 0; i < 4; i++) {
                int idx = tid + i * 128;
                int r = idx >> 4;
                int c4 = (idx & 15) * 4;
                *(float4*)&Ks[r][c4] = *(const float4*)(g_k + gbase + (size_t)r * CDIM + c4);
                *(float4*)&Vs[r][c4] = *(const float4*)(g_v + gbase + (size_t)r * CDIM + c4);
            }
        }
        __syncthreads();

        const int jmax = t - j0;  // keys j (local) with j <= jmax are visible
        float s[KV_TILE];
        float tm = -INFINITY;
#pragma unroll
        for (int j = 0; j < KV_TILE; j++) {
            float acc = 0.f;
#pragma unroll
            for (int d = 0; d < D_HEAD; d++)
                acc = fmaf(q[d], Ks[j][d], acc);
            s[j] = (j <= jmax) ? acc : -INFINITY;
            tm = fmaxf(tm, s[j]);
        }

        if (tm > -INFINITY) {
            float mnew = fmaxf(m, tm);
            float corr = __expf(m - mnew);  // first tile: exp(-inf)=0
            float lsum = 0.f;
#pragma unroll
            for (int j = 0; j < KV_TILE; j++) {
                s[j] = __expf(s[j] - mnew);  // reuse s as p
                lsum += s[j];
            }
            l = l * corr + lsum;
#pragma unroll
            for (int d = 0; d < D_HEAD; d++) o[d] *= corr;
#pragma unroll
            for (int j = 0; j < KV_TILE; j++) {
                float pj = s[j];
#pragma unroll
                for (int d = 0; d < D_HEAD; d++)
                    o[d] = fmaf(pj, Vs[j][d], o[d]);
            }
            m = mnew;
        }
        __syncthreads();
    }

    const float inv = 1.f / l;
    float* yrow = g_y + ((size_t)(b * T_SEQ + t)) * CDIM + h * D_HEAD;
#pragma unroll
    for (int d = 0; d < D_HEAD; d += 4) {
        float4 v = make_float4(o[d] * inv, o[d + 1] * inv, o[d + 2] * inv, o[d + 3] * inv);
        *(float4*)(yrow + d) = v;
    }
}

// ---------------------------------------------------------------------------
extern "C" void kernel_launch(void* const* d_in, const int* in_sizes, int n_in,
                              void* d_out, int out_size)
{
    const float* x  = (const float*)d_in[0];
    const float* Wq = (const float*)d_in[1];
    const float* Wk = (const float*)d_in[2];
    const float* Wv = (const float*)d_in[3];
    const float* Wo = (const float*)d_in[4];
    const float* bo = (const float*)d_in[5];
    float* out = (float*)d_out;

    (void)in_sizes; (void)n_in; (void)out_size;

    dim3 gemm_grid(CDIM / 128, MDIM / 128);      // 8 x 32
    dim3 qkv_grid(CDIM / 128, MDIM / 128, 3);    // 8 x 32 x 3
    dim3 attn_grid(T_SEQ / 128, N_H, 2);         // 16 x 16 x 2

    qkv_gemm_kernel<<<qkv_grid, 256>>>(x, Wq, Wk, Wv);
    flash_kernel<<<attn_grid, 128>>>();
    out_gemm_kernel<<<gemm_grid, 256>>>(Wo, bo, out);
}

// round 2
// speedup vs baseline: 4.7400x; 4.7400x over previous
#include <cuda_runtime.h>
#include <math.h>

#define MDIM 4096
#define CDIM 1024
#define T_SEQ 2048
#define N_H 16
#define D_HEAD 64

typedef unsigned int u32;

// Scratch (device globals; allocation-free per harness rules)
__device__ float g_q[MDIM * CDIM];
__device__ float g_k[MDIM * CDIM];
__device__ float g_v[MDIM * CDIM];
__device__ float g_y[MDIM * CDIM];

// ---------------------------------------------------------------------------
// tf32 helpers
// ---------------------------------------------------------------------------
__device__ __forceinline__ u32 f2tf(float f) {
    u32 r;
    asm("cvt.rna.tf32.f32 %0, %1;" : "=r"(r) : "f"(f));
    return r;
}

__device__ __forceinline__ void mma8(float* d, const u32* a, const u32* b) {
    asm volatile(
        "mma.sync.aligned.m16n8k8.row.col.f32.tf32.tf32.f32 "
        "{%0,%1,%2,%3}, {%4,%5,%6,%7}, {%8,%9}, {%0,%1,%2,%3};"
        : "+f"(d[0]), "+f"(d[1]), "+f"(d[2]), "+f"(d[3])
        : "r"(a[0]), "r"(a[1]), "r"(a[2]), "r"(a[3]), "r"(b[0]), "r"(b[1]));
}

// ---------------------------------------------------------------------------
// tf32 tensor-core GEMM: C[4096,1024] = A[4096,1024] @ W[1024,1024] (+bias)
// Block tile 128x128, K-tile 32, 256 threads (8 warps, 4x2), warp tile 32x64.
// Double-buffered smem. A stored [m][k] stride 36; B stored [k][n] stride 132.
// ---------------------------------------------------------------------------
#define AS_LD 36
#define BS_LD 132
#define AS_SZ (128 * AS_LD)
#define BS_SZ (32 * BS_LD)
#define GEMM_SMEM ((2 * (AS_SZ + BS_SZ)) * 4)

__device__ __forceinline__ void gemm_body_tf32(const float* __restrict__ A,
                                               const float* __restrict__ W,
                                               const float* __restrict__ bias,
                                               float* __restrict__ C)
{
    extern __shared__ u32 sm[];
    u32* As = sm;               // [2][AS_SZ]
    u32* Bs = sm + 2 * AS_SZ;   // [2][BS_SZ]

    const int tid = threadIdx.x;
    const int lane = tid & 31;
    const int warp = tid >> 5;
    const int wm = warp >> 1;       // 0..3
    const int wn = warp & 1;        // 0..1
    const int g = lane >> 2;        // 0..7
    const int t = lane & 3;         // 0..3

    const int row0 = blockIdx.y * 128;
    const int col0 = blockIdx.x * 128;

    // A load mapping: row = tid>>1, kq = (tid&1)*16, 4 x float4 along k
    const int a_row = tid >> 1;
    const int a_kq = (tid & 1) * 16;
    const float* Ag = A + (size_t)(row0 + a_row) * CDIM + a_kq;
    // B load mapping: c4 = tid&31 (float4 col), rbase = tid>>5; rows rbase+8i
    const int b_c4 = tid & 31;
    const int b_r = tid >> 5;
    const float* Bg = W + (size_t)b_r * CDIM + col0 + b_c4 * 4;

    float4 ar[4], br[4];

    float acc[2][8][4];
#pragma unroll
    for (int mt = 0; mt < 2; mt++)
#pragma unroll
        for (int nt = 0; nt < 8; nt++)
#pragma unroll
            for (int i = 0; i < 4; i++) acc[mt][nt][i] = 0.f;

    // prologue: load tile 0
#pragma unroll
    for (int i = 0; i < 4; i++) ar[i] = *(const float4*)(Ag + 4 * i);
#pragma unroll
    for (int i = 0; i < 4; i++) br[i] = *(const float4*)(Bg + (size_t)(8 * i) * CDIM);
    {
        u32* ap = As + a_row * AS_LD + a_kq;
#pragma unroll
        for (int i = 0; i < 4; i++) {
            uint4 v;
            v.x = f2tf(ar[i].x); v.y = f2tf(ar[i].y); v.z = f2tf(ar[i].z); v.w = f2tf(ar[i].w);
            *(uint4*)(ap + 4 * i) = v;
        }
        u32* bp = Bs + b_r * BS_LD + b_c4 * 4;
#pragma unroll
        for (int i = 0; i < 4; i++) {
            uint4 v;
            v.x = f2tf(br[i].x); v.y = f2tf(br[i].y); v.z = f2tf(br[i].z); v.w = f2tf(br[i].w);
            *(uint4*)(bp + (size_t)(8 * i) * BS_LD) = v;
        }
    }
    __syncthreads();

    for (int kt = 0; kt < 32; kt++) {
        const int cur = kt & 1;
        if (kt < 31) {
            const int k0 = (kt + 1) * 32;
#pragma unroll
            for (int i = 0; i < 4; i++) ar[i] = *(const float4*)(Ag + k0 + 4 * i);
#pragma unroll
            for (int i = 0; i < 4; i++) br[i] = *(const float4*)(Bg + (size_t)(k0 + 8 * i) * CDIM);
        }
        const u32* Ab = As + cur * AS_SZ + (wm * 32) * AS_LD;
        const u32* Bb = Bs + cur * BS_SZ + wn * 64;
#pragma unroll
        for (int kk = 0; kk < 4; kk++) {
            u32 af[2][4];
#pragma unroll
            for (int mt = 0; mt < 2; mt++) {
                const u32* p = Ab + (mt * 16 + g) * AS_LD + kk * 8 + t;
                af[mt][0] = p[0];
                af[mt][1] = p[8 * AS_LD];
                af[mt][2] = p[4];
                af[mt][3] = p[8 * AS_LD + 4];
            }
#pragma unroll
            for (int nt = 0; nt < 8; nt++) {
                u32 bf[2];
                const u32* p = Bb + (kk * 8 + t) * BS_LD + nt * 8 + g;
                bf[0] = p[0];
                bf[1] = p[4 * BS_LD];
#pragma unroll
                for (int mt = 0; mt < 2; mt++)
                    mma8(acc[mt][nt], af[mt], bf);
            }
        }
        if (kt < 31) {
            const int nbuf = (kt + 1) & 1;
            u32* ap = As + nbuf * AS_SZ + a_row * AS_LD + a_kq;
#pragma unroll
            for (int i = 0; i < 4; i++) {
                uint4 v;
                v.x = f2tf(ar[i].x); v.y = f2tf(ar[i].y); v.z = f2tf(ar[i].z); v.w = f2tf(ar[i].w);
                *(uint4*)(ap + 4 * i) = v;
            }
            u32* bp = Bs + nbuf * BS_SZ + b_r * BS_LD + b_c4 * 4;
#pragma unroll
            for (int i = 0; i < 4; i++) {
                uint4 v;
                v.x = f2tf(br[i].x); v.y = f2tf(br[i].y); v.z = f2tf(br[i].z); v.w = f2tf(br[i].w);
                *(uint4*)(bp + (size_t)(8 * i) * BS_LD) = v;
            }
            __syncthreads();
        }
    }

    // epilogue
#pragma unroll
    for (int mt = 0; mt < 2; mt++) {
#pragma unroll
        for (int nt = 0; nt < 8; nt++) {
            const int r = row0 + wm * 32 + mt * 16 + g;
            const int c = col0 + wn * 64 + nt * 8 + t * 2;
            float b0 = bias ? bias[c] : 0.f;
            float b1 = bias ? bias[c + 1] : 0.f;
            *(float2*)(C + (size_t)r * CDIM + c) =
                make_float2(acc[mt][nt][0] + b0, acc[mt][nt][1] + b1);
            *(float2*)(C + (size_t)(r + 8) * CDIM + c) =
                make_float2(acc[mt][nt][2] + b0, acc[mt][nt][3] + b1);
        }
    }
}

__global__ __launch_bounds__(256) void qkv_gemm_kernel(const float* __restrict__ x,
                                                       const float* __restrict__ Wq,
                                                       const float* __restrict__ Wk,
                                                       const float* __restrict__ Wv)
{
    const float* W = (blockIdx.z == 0) ? Wq : (blockIdx.z == 1) ? Wk : Wv;
    float* C = (blockIdx.z == 0) ? g_q : (blockIdx.z == 1) ? g_k : g_v;
    gemm_body_tf32(x, W, nullptr, C);
}

__global__ __launch_bounds__(256) void out_gemm_kernel(const float* __restrict__ Wo,
                                                       const float* __restrict__ bo,
                                                       float* __restrict__ out)
{
    gemm_body_tf32(g_y, Wo, bo, out);
}

// ---------------------------------------------------------------------------
// Flash attention, tf32 tensor cores, causal.
// Block: 128 threads (4 warps). Q block = 64 rows (16 per warp). KV tile 64.
// S = Q K^T via mma (Q frags in regs, K in smem), online softmax in regs,
// P staged via warp-private smem (layout conversion), O += P V via mma.
// grid: (T/64, H, B)
// ---------------------------------------------------------------------------
#define KS_LD 68
#define VS_LD 68
#define PS_LD 68
#define FK_SZ (64 * KS_LD)
#define FV_SZ (64 * VS_LD)
#define FP_SZ (16 * PS_LD)
#define FLASH_SMEM ((FK_SZ + FV_SZ + 4 * FP_SZ) * 4)

__global__ __launch_bounds__(128) void flash_tf32_kernel()
{
    extern __shared__ u32 sm[];
    u32* Ks = sm;
    u32* Vs = sm + FK_SZ;
    u32* Ps = sm + FK_SZ + FV_SZ;

    const int tid = threadIdx.x;
    const int lane = tid & 31;
    const int warp = tid >> 5;
    const int g = lane >> 2;
    const int t = lane & 3;
    const int b = blockIdx.z;
    const int h = blockIdx.y;
    const int q0 = blockIdx.x * 64;
    const int qw = q0 + warp * 16;

    // Q fragments (pre-scaled by 1/sqrt(64), tf32)
    const float* Qg = g_q + ((size_t)(b * T_SEQ + qw)) * CDIM + h * D_HEAD;
    u32 qa[8][4];
#pragma unroll
    for (int kc = 0; kc < 8; kc++) {
        qa[kc][0] = f2tf(0.125f * Qg[(size_t)g * CDIM + kc * 8 + t]);
        qa[kc][1] = f2tf(0.125f * Qg[(size_t)(g + 8) * CDIM + kc * 8 + t]);
        qa[kc][2] = f2tf(0.125f * Qg[(size_t)g * CDIM + kc * 8 + t + 4]);
        qa[kc][3] = f2tf(0.125f * Qg[(size_t)(g + 8) * CDIM + kc * 8 + t + 4]);
    }

    float o[8][4];
#pragma unroll
    for (int nt = 0; nt < 8; nt++)
#pragma unroll
        for (int i = 0; i < 4; i++) o[nt][i] = 0.f;
    float m0 = -INFINITY, m1 = -INFINITY, l0 = 0.f, l1 = 0.f;

    const int ntiles = blockIdx.x + 1;
    const float* Kg = g_k + ((size_t)(b * T_SEQ)) * CDIM + h * D_HEAD;
    const float* Vg = g_v + ((size_t)(b * T_SEQ)) * CDIM + h * D_HEAD;
    u32* Pw = Ps + warp * FP_SZ;

#pragma unroll 1
    for (int tile = 0; tile < ntiles; tile++) {
        const int j0 = tile * 64;
        __syncthreads();
        // cooperative load K,V tile (64x64 each) with tf32 convert
#pragma unroll
        for (int i = 0; i < 8; i++) {
            const int idx = tid + i * 128;
            const int r = idx >> 4;
            const int c4 = (idx & 15) * 4;
            float4 kv = *(const float4*)(Kg + (size_t)(j0 + r) * CDIM + c4);
            float4 vv = *(const float4*)(Vg + (size_t)(j0 + r) * CDIM + c4);
            u32* kp = Ks + r * KS_LD + c4;
            kp[0] = f2tf(kv.x); kp[1] = f2tf(kv.y); kp[2] = f2tf(kv.z); kp[3] = f2tf(kv.w);
            u32* vp = Vs + r * VS_LD + c4;
            vp[0] = f2tf(vv.x); vp[1] = f2tf(vv.y); vp[2] = f2tf(vv.z); vp[3] = f2tf(vv.w);
        }
        __syncthreads();

        // S = Q K^T  (16 x 64 per warp)
        float s[8][4];
#pragma unroll
        for (int nt = 0; nt < 8; nt++)
#pragma unroll
            for (int i = 0; i < 4; i++) s[nt][i] = 0.f;
#pragma unroll
        for (int kc = 0; kc < 8; kc++) {
#pragma unroll
            for (int nt = 0; nt < 8; nt++) {
                u32 bf[2];
                const u32* p = Ks + (nt * 8 + g) * KS_LD + kc * 8 + t;
                bf[0] = p[0];
                bf[1] = p[4];
                mma8(s[nt], qa[kc], bf);
            }
        }

        // causal mask (only the diagonal tile needs it)
        if (tile == ntiles - 1) {
#pragma unroll
            for (int nt = 0; nt < 8; nt++) {
                const int cb = j0 + nt * 8 + 2 * t;
                if (cb     > qw + g)     s[nt][0] = -INFINITY;
                if (cb + 1 > qw + g)     s[nt][1] = -INFINITY;
                if (cb     > qw + g + 8) s[nt][2] = -INFINITY;
                if (cb + 1 > qw + g + 8) s[nt][3] = -INFINITY;
            }
        }

        // online softmax (rows g and g+8)
        float mx0 = -INFINITY, mx1 = -INFINITY;
#pragma unroll
        for (int nt = 0; nt < 8; nt++) {
            mx0 = fmaxf(mx0, fmaxf(s[nt][0], s[nt][1]));
            mx1 = fmaxf(mx1, fmaxf(s[nt][2], s[nt][3]));
        }
        mx0 = fmaxf(mx0, __shfl_xor_sync(0xffffffffu, mx0, 1));
        mx0 = fmaxf(mx0, __shfl_xor_sync(0xffffffffu, mx0, 2));
        mx1 = fmaxf(mx1, __shfl_xor_sync(0xffffffffu, mx1, 1));
        mx1 = fmaxf(mx1, __shfl_xor_sync(0xffffffffu, mx1, 2));

        const float mn0 = fmaxf(m0, mx0);
        const float mn1 = fmaxf(m1, mx1);
        const float cr0 = __expf(m0 - mn0);
        const float cr1 = __expf(m1 - mn1);
        float sum0 = 0.f, sum1 = 0.f;
#pragma unroll
        for (int nt = 0; nt < 8; nt++) {
            s[nt][0] = __expf(s[nt][0] - mn0);
            s[nt][1] = __expf(s[nt][1] - mn0);
            s[nt][2] = __expf(s[nt][2] - mn1);
            s[nt][3] = __expf(s[nt][3] - mn1);
            sum0 += s[nt][0] + s[nt][1];
            sum1 += s[nt][2] + s[nt][3];
        }
        sum0 += __shfl_xor_sync(0xffffffffu, sum0, 1);
        sum0 += __shfl_xor_sync(0xffffffffu, sum0, 2);
        sum1 += __shfl_xor_sync(0xffffffffu, sum1, 1);
        sum1 += __shfl_xor_sync(0xffffffffu, sum1, 2);
        l0 = l0 * cr0 + sum0;
        l1 = l1 * cr1 + sum1;
        m0 = mn0;
        m1 = mn1;
#pragma unroll
        for (int nt = 0; nt < 8; nt++) {
            o[nt][0] *= cr0;
            o[nt][1] *= cr0;
            o[nt][2] *= cr1;
            o[nt][3] *= cr1;
        }

        // stage P (tf32) into warp-private smem
#pragma unroll
        for (int nt = 0; nt < 8; nt++) {
            uint2 v0, v1;
            v0.x = f2tf(s[nt][0]); v0.y = f2tf(s[nt][1]);
            v1.x = f2tf(s[nt][2]); v1.y = f2tf(s[nt][3]);
            *(uint2*)(Pw + g * PS_LD + nt * 8 + 2 * t) = v0;
            *(uint2*)(Pw + (g + 8) * PS_LD + nt * 8 + 2 * t) = v1;
        }
        __syncwarp();

        // O += P V
#pragma unroll
        for (int kc = 0; kc < 8; kc++) {
            u32 af[4];
            const u32* p = Pw + g * PS_LD + kc * 8 + t;
            af[0] = p[0];
            af[1] = p[8 * PS_LD];
            af[2] = p[4];
            af[3] = p[8 * PS_LD + 4];
#pragma unroll
            for (int nt = 0; nt < 8; nt++) {
                u32 bf[2];
                const u32* vp = Vs + (kc * 8 + t) * VS_LD + nt * 8 + g;
                bf[0] = vp[0];
                bf[1] = vp[4 * VS_LD];
                mma8(o[nt], af, bf);
            }
        }
        __syncwarp();
    }

    // normalize + write
    const float inv0 = 1.f / l0;
    const float inv1 = 1.f / l1;
    float* Yg = g_y + ((size_t)(b * T_SEQ + qw)) * CDIM + h * D_HEAD;
#pragma unroll
    for (int nt = 0; nt < 8; nt++) {
        const int c = nt * 8 + 2 * t;
        *(float2*)(Yg + (size_t)g * CDIM + c) =
            make_float2(o[nt][0] * inv0, o[nt][1] * inv0);
        *(float2*)(Yg + (size_t)(g + 8) * CDIM + c) =
            make_float2(o[nt][2] * inv1, o[nt][3] * inv1);
    }
}

// ---------------------------------------------------------------------------
extern "C" void kernel_launch(void* const* d_in, const int* in_sizes, int n_in,
                              void* d_out, int out_size)
{
    const float* x  = (const float*)d_in[0];
    const float* Wq = (const float*)d_in[1];
    const float* Wk = (const float*)d_in[2];
    const float* Wv = (const float*)d_in[3];
    const float* Wo = (const float*)d_in[4];
    const float* bo = (const float*)d_in[5];
    float* out = (float*)d_out;
    (void)in_sizes; (void)n_in; (void)out_size;

    cudaFuncSetAttribute(qkv_gemm_kernel, cudaFuncAttributeMaxDynamicSharedMemorySize, GEMM_SMEM);
    cudaFuncSetAttribute(out_gemm_kernel, cudaFuncAttributeMaxDynamicSharedMemorySize, GEMM_SMEM);
    cudaFuncSetAttribute(flash_tf32_kernel, cudaFuncAttributeMaxDynamicSharedMemorySize, FLASH_SMEM);

    dim3 qkv_grid(CDIM / 128, MDIM / 128, 3);    // 8 x 32 x 3
    dim3 gemm_grid(CDIM / 128, MDIM / 128);      // 8 x 32
    dim3 attn_grid(T_SEQ / 64, N_H, 2);          // 32 x 16 x 2

    qkv_gemm_kernel<<<qkv_grid, 256, GEMM_SMEM>>>(x, Wq, Wk, Wv);
    flash_tf32_kernel<<<attn_grid, 128, FLASH_SMEM>>>();
    out_gemm_kernel<<<gemm_grid, 256, GEMM_SMEM>>>(Wo, bo, out);
}